// round 2
// baseline (speedup 1.0000x reference)
#include <cuda_runtime.h>
#include <math.h>
#include <stdint.h>

typedef unsigned long long u64;

#define CAP 65536

// ---- device scratch (no allocations allowed) ----
__device__ float g_imgup[2896*2896];
__device__ float g_img2 [1448*1448];
__device__ float g_img3 [1023*1023];
__device__ float g_img4 [723*723];
__device__ float g_img5 [511*511];
__device__ float g_blurA[2048*2048];
__device__ float g_blurB[2048*2048];
__device__ float g_score[2896*2896];
__device__ float g_rmax [2896*2896];
__device__ u64   g_cand[6*CAP];
__device__ u64   g_pool[12288];
__device__ u64   g_final[2048];
__device__ int   g_cnt[8];   // [0..5]=per-level cand count, [6]=pool, [7]=final

__constant__ int   c_W[6]    = {2896,2048,1448,1023,723,511};
__constant__ float c_fact[6] = {(float)(2048.0/2896.0), 1.0f, (float)(2048.0/1448.0),
                                (float)(2048.0/1023.0), (float)(2048.0/723.0), (float)(2048.0/511.0)};
__constant__ float c_scal[6] = {(float)(2048.0/2896.0*22.0), 22.0f, (float)(2048.0/1448.0*22.0),
                                (float)(2048.0/1023.0*22.0), (float)(2048.0/723.0*22.0), (float)(2048.0/511.0*22.0)};

__global__ void k_zero()
{
    if (threadIdx.x < 8) g_cnt[threadIdx.x] = 0;
}

// ---------------------------------------------------------------------------
// jax.image.resize bilinear, antialias=False: sample=(i+0.5)*inv-0.5, triangle
// weights renormalized over in-range taps. H interpolation first, then W.
__global__ void k_resize(const float* __restrict__ in, int sw, int sh,
                         float* __restrict__ dst, int dw, int dh, float invs)
{
    int idx = blockIdx.x * blockDim.x + threadIdx.x;
    if (idx >= dw * dh) return;
    int dy = idx / dw, dx = idx - dy * dw;

    float sy = __fadd_rn(__fmul_rn(__fadd_rn((float)dy, 0.5f), invs), -0.5f);
    float sx = __fadd_rn(__fmul_rn(__fadd_rn((float)dx, 0.5f), invs), -0.5f);
    int jy0 = (int)floorf(sy), jy1 = jy0 + 1;
    int jx0 = (int)floorf(sx), jx1 = jx0 + 1;
    float wy0 = __fadd_rn(1.0f, -__fadd_rn(sy, -(float)jy0));
    float wy1 = __fadd_rn(1.0f, -__fadd_rn((float)jy1, -sy));
    float wx0 = __fadd_rn(1.0f, -__fadd_rn(sx, -(float)jx0));
    float wx1 = __fadd_rn(1.0f, -__fadd_rn((float)jx1, -sx));
    bool vy0 = (jy0 >= 0), vy1 = (jy1 <= sh - 1);
    bool vx0 = (jx0 >= 0), vx1 = (jx1 <= sw - 1);
    int cy0 = vy0 ? jy0 : 0, cy1 = vy1 ? jy1 : sh - 1;
    int cx0 = vx0 ? jx0 : 0, cx1 = vx1 ? jx1 : sw - 1;

    float p00 = __ldg(in + (size_t)cy0 * sw + cx0);
    float p01 = __ldg(in + (size_t)cy0 * sw + cx1);
    float p10 = __ldg(in + (size_t)cy1 * sw + cx0);
    float p11 = __ldg(in + (size_t)cy1 * sw + cx1);

    float c0, c1;
    if (vy0 && vy1) {
        float tot = __fadd_rn(wy0, wy1);
        float n0 = __fdiv_rn(wy0, tot), n1 = __fdiv_rn(wy1, tot);
        c0 = __fadd_rn(__fmul_rn(n0, p00), __fmul_rn(n1, p10));
        c1 = __fadd_rn(__fmul_rn(n0, p01), __fmul_rn(n1, p11));
    } else if (vy0) { c0 = p00; c1 = p01; }
    else            { c0 = p10; c1 = p11; }

    float v;
    if (vx0 && vx1) {
        float tot = __fadd_rn(wx0, wx1);
        float n0 = __fdiv_rn(wx0, tot), n1 = __fdiv_rn(wx1, tot);
        v = __fadd_rn(__fmul_rn(n0, c0), __fmul_rn(n1, c1));
    } else if (vx0) v = c0; else v = c1;

    dst[idx] = v;
}

// ---------------------------------------------------------------------------
__device__ __forceinline__ int reflect_i(int i, int n)
{
    if (i < 0) return -i;
    if (i >= n) return 2 * n - 2 - i;
    return i;
}

__global__ void k_blurV(const float* __restrict__ in, float* __restrict__ out,
                        int W, int H, float g0, float g1, float g2)
{
    int idx = blockIdx.x * blockDim.x + threadIdx.x;
    if (idx >= W * H) return;
    int y = idx / W, x = idx - y * W;
    float a =      g0 * __ldg(in + (size_t)reflect_i(y - 2, H) * W + x);
    a = fmaf(g1, __ldg(in + (size_t)reflect_i(y - 1, H) * W + x), a);
    a = fmaf(g2, __ldg(in + (size_t)y * W + x), a);
    a = fmaf(g1, __ldg(in + (size_t)reflect_i(y + 1, H) * W + x), a);
    a = fmaf(g0, __ldg(in + (size_t)reflect_i(y + 2, H) * W + x), a);
    out[idx] = a;
}

__global__ void k_blurH(const float* __restrict__ in, float* __restrict__ out,
                        int W, int H, float g0, float g1, float g2)
{
    int idx = blockIdx.x * blockDim.x + threadIdx.x;
    if (idx >= W * H) return;
    int y = idx / W, x = idx - y * W;
    const float* r = in + (size_t)y * W;
    float a =      g0 * __ldg(r + reflect_i(x - 2, W));
    a = fmaf(g1, __ldg(r + reflect_i(x - 1, W)), a);
    a = fmaf(g2, __ldg(r + x), a);
    a = fmaf(g1, __ldg(r + reflect_i(x + 1, W)), a);
    a = fmaf(g0, __ldg(r + reflect_i(x + 2, W)), a);
    out[idx] = a;
}

// ---------------------------------------------------------------------------
// 5x5 correlation + 15px border mask. Only interior [15,H-15)x[15,W-15)
// is nonzero, so all taps are in-bounds on the compute path.
__global__ void __launch_bounds__(128) k_conv(const float* __restrict__ img,
                       const float* __restrict__ wp, const float* __restrict__ bp,
                       float* __restrict__ score, int W, int H)
{
    __shared__ float sw[25];
    __shared__ float sb;
    int t = threadIdx.x;
    if (t < 25) sw[t] = __ldg(wp + t);
    if (t == 31) sb = __ldg(bp);
    __syncthreads();

    int y  = blockIdx.y;
    int x0 = (blockIdx.x * 128 + t) * 8;
    if (x0 >= W) return;
    float* orow = score + (size_t)y * W;

    bool rowZero = (y < 15 || y >= H - 15);
    bool strip   = (x0 >= 8 && x0 <= W - 16);
    if (rowZero || !strip) {
        #pragma unroll
        for (int o = 0; o < 8; ++o) { int x = x0 + o; if (x < W) orow[x] = 0.f; }
        return;
    }
    float acc[8];
    #pragma unroll
    for (int o = 0; o < 8; ++o) acc[o] = sb;
    #pragma unroll
    for (int ky = 0; ky < 5; ++ky) {
        const float* r = img + (size_t)(y + ky - 2) * W + (x0 - 2);
        float v[12];
        #pragma unroll
        for (int j = 0; j < 12; ++j) v[j] = __ldg(r + j);
        #pragma unroll
        for (int kx = 0; kx < 5; ++kx) {
            float w = sw[ky * 5 + kx];
            #pragma unroll
            for (int o = 0; o < 8; ++o) acc[o] = fmaf(w, v[o + kx], acc[o]);
        }
    }
    #pragma unroll
    for (int o = 0; o < 8; ++o) {
        int x = x0 + o;
        orow[x] = (x >= 15 && x < W - 15) ? acc[o] : 0.f;
    }
}

// ---------------------------------------------------------------------------
// Row max over [x-7,x+7], clamped (duplicates never change a max).
__global__ void __launch_bounds__(128) k_nmsrow(const float* __restrict__ ms,
                                                float* __restrict__ rmax, int W, int H)
{
    int y  = blockIdx.y;
    int x0 = (blockIdx.x * 128 + threadIdx.x) * 8;
    if (x0 >= W) return;
    const float* r = ms + (size_t)y * W;
    float v[22];
    if (x0 >= 8 && x0 <= W - 15) {
        #pragma unroll
        for (int j = 0; j < 22; ++j) v[j] = __ldg(r + (x0 - 7 + j));
    } else {
        #pragma unroll
        for (int j = 0; j < 22; ++j) {
            int xx = x0 - 7 + j;
            xx = xx < 0 ? 0 : (xx > W - 1 ? W - 1 : xx);
            v[j] = __ldg(r + xx);
        }
    }
    float* orow = rmax + (size_t)y * W;
    #pragma unroll
    for (int o = 0; o < 8; ++o) {
        int x = x0 + o;
        if (x >= W) break;
        float m = v[o];
        #pragma unroll
        for (int j = 1; j < 15; ++j) m = fmaxf(m, v[o + j]);
        orow[x] = m;
    }
}

// ---------------------------------------------------------------------------
// Column max of rmax over [y-7,y+7] + candidate extraction.
// Key: scoreBits<<26 | (5-level)<<23 | (0x7FFFFF - pixIdx)  (max-order == top_k order)
__global__ void __launch_bounds__(128) k_nmscol(const float* __restrict__ ms,
                                                const float* __restrict__ rmax,
                                                int W, int H, int level)
{
    int x  = blockIdx.x * 128 + threadIdx.x;
    if (x >= W) return;
    int y0 = blockIdx.y * 8;
    float v[23];
    #pragma unroll
    for (int j = 0; j < 23; ++j) {
        int yy = y0 - 7 + j;
        yy = yy < 0 ? 0 : (yy > H - 1 ? H - 1 : yy);
        v[j] = __ldg(rmax + (size_t)yy * W + x);
    }
    #pragma unroll
    for (int o = 0; o < 8; ++o) {
        int y = y0 + o;
        if (y >= H) break;
        float m = v[o];
        #pragma unroll
        for (int j = 1; j < 15; ++j) m = fmaxf(m, v[o + j]);
        float s = __ldg(ms + (size_t)y * W + x);
        if (s > 0.0f && s == m) {
            unsigned sb = __float_as_uint(s) | 0x80000000u;
            int pix = y * W + x;
            u64 key = ((u64)sb << 26) | ((u64)(5 - level) << 23)
                    | (u64)(0x7FFFFF - pix);
            int pos = atomicAdd(&g_cnt[level], 1);
            if (pos < CAP) g_cand[(size_t)level * CAP + pos] = key;
        }
    }
}

// ---------------------------------------------------------------------------
// Single-block radix select: append the top-k keys (by max order) of src to dst.
// Keys are unique, so exactly min(k,cnt) elements satisfy key >= threshold.
__global__ void __launch_bounds__(1024) k_select(const u64* __restrict__ src, int srcCntIdx,
                                                 int k, u64* __restrict__ dst, int dstCntIdx)
{
    __shared__ int hist[256];
    __shared__ u64 s_pref;
    __shared__ int s_k;
    int tid = threadIdx.x;
    int cnt = g_cnt[srcCntIdx];
    if (cnt > CAP) cnt = CAP;
    u64 thr = 0;
    if (cnt > k) {
        if (tid == 0) { s_pref = 0ull; s_k = k; }
        __syncthreads();
        for (int b = 7; b >= 0; --b) {
            if (tid < 256) hist[tid] = 0;
            __syncthreads();
            u64 pref = s_pref;
            u64 maskHi = (b == 7) ? 0ull : (~0ull << (8 * (b + 1)));
            for (int i = tid; i < cnt; i += 1024) {
                u64 key = src[i];
                if ((key & maskHi) == pref)
                    atomicAdd(&hist[(int)((key >> (8 * b)) & 255)], 1);
            }
            __syncthreads();
            if (tid == 0) {
                int kk = s_k, cum = 0, d = 255;
                for (; d >= 0; --d) { cum += hist[d]; if (cum >= kk) break; }
                s_k = kk - (cum - hist[d]);
                s_pref = s_pref | ((u64)d << (8 * b));
            }
            __syncthreads();
        }
        thr = s_pref;
    }
    __syncthreads();
    for (int i = tid; i < cnt; i += 1024) {
        u64 key = src[i];
        if (key >= thr) {
            int p = atomicAdd(&g_cnt[dstCntIdx], 1);
            dst[p] = key;
        }
    }
}

// ---------------------------------------------------------------------------
// Bitonic sort the 2048 selected keys (ascending, read reversed = descending),
// decode, and emit lafs [2048,2,3] then responses [2048].
__global__ void __launch_bounds__(1024) k_sort_emit(float* __restrict__ out, int out_size)
{
    __shared__ u64 s[2048];
    int tid = threadIdx.x;
    int cnt = g_cnt[7];
    if (cnt > 2048) cnt = 2048;
    s[tid]        = (tid < cnt)        ? g_final[tid]        : 0ull;
    s[tid + 1024] = (tid + 1024 < cnt) ? g_final[tid + 1024] : 0ull;
    __syncthreads();
    for (int ksz = 2; ksz <= 2048; ksz <<= 1) {
        for (int j = ksz >> 1; j > 0; j >>= 1) {
            #pragma unroll
            for (int half = 0; half < 2; ++half) {
                int i = tid + half * 1024;
                int ixj = i ^ j;
                if (ixj > i) {
                    u64 a = s[i], b = s[ixj];
                    bool asc = ((i & ksz) == 0);
                    if (asc ? (a > b) : (a < b)) { s[i] = b; s[ixj] = a; }
                }
            }
            __syncthreads();
        }
    }
    bool haveL = (out_size >= 12288);
    bool haveR = (out_size >= 14336) || (out_size < 12288);
    int rbase = (out_size >= 14336) ? 12288 : 0;
    for (int r = tid; r < 2048; r += 1024) {
        u64 key = s[2047 - r];
        int pix = 0x7FFFFF - (int)(key & 0x7FFFFF);
        int lvl = 5 - (int)((key >> 23) & 7);
        float sc = __uint_as_float((unsigned)(key >> 26) & 0x7FFFFFFFu);
        int Wl = c_W[lvl];
        int py = pix / Wl, px = pix - py * Wl;
        float f  = c_fact[lvl], sg = c_scal[lvl];
        float fx = __fmul_rn((float)px, f);
        float fy = __fmul_rn((float)py, f);
        if (haveL) {
            float* L = out + (size_t)r * 6;
            L[0] = sg; L[1] = 0.f; L[2] = fx;
            L[3] = 0.f; L[4] = sg; L[5] = fy;
        }
        if (haveR) out[rbase + r] = sc;
    }
}

// ---------------------------------------------------------------------------
extern "C" void kernel_launch(void* const* d_in, const int* in_sizes, int n_in,
                              void* d_out, int out_size)
{
    const float* img = (const float*)d_in[0];
    const float* cw  = (const float*)d_in[1];
    const float* cb  = (const float*)d_in[2];
    float* out = (float*)d_out;

    void *p_up, *p_i2, *p_i3, *p_i4, *p_i5, *p_bA, *p_bB, *p_sc, *p_rm, *p_cd, *p_pl, *p_fn;
    cudaGetSymbolAddress(&p_up, g_imgup);
    cudaGetSymbolAddress(&p_i2, g_img2);
    cudaGetSymbolAddress(&p_i3, g_img3);
    cudaGetSymbolAddress(&p_i4, g_img4);
    cudaGetSymbolAddress(&p_i5, g_img5);
    cudaGetSymbolAddress(&p_bA, g_blurA);
    cudaGetSymbolAddress(&p_bB, g_blurB);
    cudaGetSymbolAddress(&p_sc, g_score);
    cudaGetSymbolAddress(&p_rm, g_rmax);
    cudaGetSymbolAddress(&p_cd, g_cand);
    cudaGetSymbolAddress(&p_pl, g_pool);
    cudaGetSymbolAddress(&p_fn, g_final);
    float *imgup=(float*)p_up, *img2=(float*)p_i2, *img3=(float*)p_i3,
          *img4=(float*)p_i4, *img5=(float*)p_i5, *bA=(float*)p_bA, *bB=(float*)p_bB,
          *sc=(float*)p_sc, *rm=(float*)p_rm;
    u64 *cand=(u64*)p_cd, *pool=(u64*)p_pl, *fin=(u64*)p_fn;

    // gaussian 5-tap, sigma=1 (numpy float32 math)
    float gx[5] = {4.f, 1.f, 0.f, 1.f, 4.f};
    float g[5], gs = 0.f;
    for (int i = 0; i < 5; ++i) { g[i] = expf(-gx[i] * 0.5f); gs += g[i]; }
    for (int i = 0; i < 5; ++i) g[i] /= gs;

    const int   Ws[6] = {2896, 2048, 1448, 1023, 723, 511};
    const int   kk[6] = {1040, 1560, 1820, 1950, 2015, 2047};
    const float* lvlImg[6];
    lvlImg[0] = imgup; lvlImg[1] = img; lvlImg[2] = img2;
    lvlImg[3] = img3;  lvlImg[4] = img4; lvlImg[5] = img5;

    k_zero<<<1, 32>>>();

    // build level images
    {
        int n = 2896 * 2896;
        k_resize<<<(n + 255) / 256, 256>>>(img, 2048, 2048, imgup, 2896, 2896,
                                           (float)(2048.0 / 2896.0));
    }
    const float* src = img;
    float* dsts[4] = {img2, img3, img4, img5};
    for (int i = 0; i < 4; ++i) {
        int sw = Ws[i + 1], dw = Ws[i + 2];
        int ns = sw * sw, nd = dw * dw;
        k_blurV<<<(ns + 255) / 256, 256>>>(src, bA, sw, sw, g[0], g[1], g[2]);
        k_blurH<<<(ns + 255) / 256, 256>>>(bA, bB, sw, sw, g[0], g[1], g[2]);
        k_resize<<<(nd + 255) / 256, 256>>>(bB, sw, sw, dsts[i], dw, dw,
                                            (float)((double)sw / (double)dw));
        src = dsts[i];
    }

    // detect on every level
    for (int l = 0; l < 6; ++l) {
        int W = Ws[l];
        dim3 gs2((W + 1023) / 1024, W);
        k_conv  <<<gs2, 128>>>(lvlImg[l], cw, cb, sc, W, W);
        k_nmsrow<<<gs2, 128>>>(sc, rm, W, W);
        dim3 gc((W + 127) / 128, (W + 7) / 8);
        k_nmscol<<<gc, 128>>>(sc, rm, W, W, l);
        k_select<<<1, 1024>>>(cand + (size_t)l * CAP, l, kk[l], pool, 6);
    }

    // global top-2048, sort, emit
    k_select<<<1, 1024>>>(pool, 6, 2048, fin, 7);
    k_sort_emit<<<1, 1024>>>(out, out_size);
}

// round 3
// speedup vs baseline: 1.5231x; 1.5231x over previous
#include <cuda_runtime.h>
#include <math.h>
#include <stdint.h>

typedef unsigned long long u64;

#define CAP 65536

// ---- device scratch (no allocations allowed) ----
__device__ float g_imgup[2896*2896];
__device__ float g_img2 [1448*1448];
__device__ float g_img3 [1024*1023];
__device__ float g_img4 [724*723];
__device__ float g_img5 [512*511];
__device__ float g_blurA[2048*2048];
__device__ float g_blurB[2048*2048];
__device__ float g_score[2896*2896];
__device__ float g_rmax [2896*2896];
__device__ u64   g_cand[6*CAP];
__device__ u64   g_pool[12288];
__device__ int   g_cnt[8];   // [0..5]=per-level cand count, [6]=pool

__constant__ int   c_W[6]    = {2896,2048,1448,1023,723,511};
__constant__ float c_fact[6] = {(float)(2048.0/2896.0), 1.0f, (float)(2048.0/1448.0),
                                (float)(2048.0/1023.0), (float)(2048.0/723.0), (float)(2048.0/511.0)};
__constant__ float c_scal[6] = {(float)(2048.0/2896.0*22.0), 22.0f, (float)(2048.0/1448.0*22.0),
                                (float)(2048.0/1023.0*22.0), (float)(2048.0/723.0*22.0), (float)(2048.0/511.0*22.0)};
__constant__ int   c_k[6]    = {1040,1560,1820,1950,2015,2047};

__device__ __forceinline__ float4 f4max(float4 a, float4 b)
{
    return make_float4(fmaxf(a.x,b.x), fmaxf(a.y,b.y), fmaxf(a.z,b.z), fmaxf(a.w,b.w));
}

__global__ void k_zero()
{
    if (threadIdx.x < 8) g_cnt[threadIdx.x] = 0;
}

// ---------------------------------------------------------------------------
// jax.image.resize bilinear, antialias=False: sample=(i+0.5)*inv-0.5, triangle
// weights renormalized over in-range taps. H interpolation first, then W.
__global__ void __launch_bounds__(256) k_resize(const float* __restrict__ in, int sIn,
                         int sw, int sh, float* __restrict__ dst, int sOut, int dw,
                         float invs)
{
    int dx = blockIdx.x * 256 + threadIdx.x;
    int dy = blockIdx.y;
    if (dx >= dw) return;

    float sy = __fadd_rn(__fmul_rn(__fadd_rn((float)dy, 0.5f), invs), -0.5f);
    float sx = __fadd_rn(__fmul_rn(__fadd_rn((float)dx, 0.5f), invs), -0.5f);
    int jy0 = (int)floorf(sy), jy1 = jy0 + 1;
    int jx0 = (int)floorf(sx), jx1 = jx0 + 1;
    float wy0 = __fadd_rn(1.0f, -__fadd_rn(sy, -(float)jy0));
    float wy1 = __fadd_rn(1.0f, -__fadd_rn((float)jy1, -sy));
    float wx0 = __fadd_rn(1.0f, -__fadd_rn(sx, -(float)jx0));
    float wx1 = __fadd_rn(1.0f, -__fadd_rn((float)jx1, -sx));
    bool vy0 = (jy0 >= 0), vy1 = (jy1 <= sh - 1);
    bool vx0 = (jx0 >= 0), vx1 = (jx1 <= sw - 1);
    int cy0 = vy0 ? jy0 : 0, cy1 = vy1 ? jy1 : sh - 1;
    int cx0 = vx0 ? jx0 : 0, cx1 = vx1 ? jx1 : sw - 1;

    float p00 = __ldg(in + (size_t)cy0 * sIn + cx0);
    float p01 = __ldg(in + (size_t)cy0 * sIn + cx1);
    float p10 = __ldg(in + (size_t)cy1 * sIn + cx0);
    float p11 = __ldg(in + (size_t)cy1 * sIn + cx1);

    float c0, c1;
    if (vy0 && vy1) {
        float tot = __fadd_rn(wy0, wy1);
        float n0 = __fdiv_rn(wy0, tot), n1 = __fdiv_rn(wy1, tot);
        c0 = __fadd_rn(__fmul_rn(n0, p00), __fmul_rn(n1, p10));
        c1 = __fadd_rn(__fmul_rn(n0, p01), __fmul_rn(n1, p11));
    } else if (vy0) { c0 = p00; c1 = p01; }
    else            { c0 = p10; c1 = p11; }

    float v;
    if (vx0 && vx1) {
        float tot = __fadd_rn(wx0, wx1);
        float n0 = __fdiv_rn(wx0, tot), n1 = __fdiv_rn(wx1, tot);
        v = __fadd_rn(__fmul_rn(n0, c0), __fmul_rn(n1, c1));
    } else if (vx0) v = c0; else v = c1;

    dst[(size_t)dy * sOut + dx] = v;
}

// ---------------------------------------------------------------------------
__device__ __forceinline__ int reflect_i(int i, int n)
{
    if (i < 0) return -i;
    if (i >= n) return 2 * n - 2 - i;
    return i;
}

__global__ void __launch_bounds__(128) k_blurV(const float* __restrict__ in,
                        float* __restrict__ out, int S, int W, int H,
                        float g0, float g1, float g2)
{
    int x4 = (blockIdx.x * 128 + threadIdx.x) * 4;
    int y  = blockIdx.y;
    if (x4 >= W) return;
    float4 a = __ldg((const float4*)(in + (size_t)reflect_i(y - 2, H) * S + x4));
    float4 b = __ldg((const float4*)(in + (size_t)reflect_i(y - 1, H) * S + x4));
    float4 c = __ldg((const float4*)(in + (size_t)y * S + x4));
    float4 d = __ldg((const float4*)(in + (size_t)reflect_i(y + 1, H) * S + x4));
    float4 e = __ldg((const float4*)(in + (size_t)reflect_i(y + 2, H) * S + x4));
    float4 r;
    r.x = fmaf(g0, e.x, fmaf(g1, d.x, fmaf(g2, c.x, fmaf(g1, b.x, g0 * a.x))));
    r.y = fmaf(g0, e.y, fmaf(g1, d.y, fmaf(g2, c.y, fmaf(g1, b.y, g0 * a.y))));
    r.z = fmaf(g0, e.z, fmaf(g1, d.z, fmaf(g2, c.z, fmaf(g1, b.z, g0 * a.z))));
    r.w = fmaf(g0, e.w, fmaf(g1, d.w, fmaf(g2, c.w, fmaf(g1, b.w, g0 * a.w))));
    *(float4*)(out + (size_t)y * S + x4) = r;
}

__global__ void __launch_bounds__(128) k_blurH(const float* __restrict__ in,
                        float* __restrict__ out, int S, int W, int H,
                        float g0, float g1, float g2)
{
    int x4 = (blockIdx.x * 128 + threadIdx.x) * 4;
    int y  = blockIdx.y;
    if (x4 >= W) return;
    const float* r = in + (size_t)y * S;
    if (x4 >= 4 && x4 + 8 <= W) {
        float4 a = __ldg((const float4*)(r + x4 - 4));
        float4 b = __ldg((const float4*)(r + x4));
        float4 c = __ldg((const float4*)(r + x4 + 4));
        float v[12] = {a.x,a.y,a.z,a.w, b.x,b.y,b.z,b.w, c.x,c.y,c.z,c.w};
        float4 o;
        float* op = (float*)&o;
        #pragma unroll
        for (int cc = 0; cc < 4; ++cc) {
            float t = fmaf(g0, v[cc + 6], fmaf(g1, v[cc + 5],
                      fmaf(g2, v[cc + 4], fmaf(g1, v[cc + 3], g0 * v[cc + 2]))));
            op[cc] = t;
        }
        *(float4*)(out + (size_t)y * S + x4) = o;
    } else {
        for (int cc = 0; cc < 4; ++cc) {
            int x = x4 + cc;
            if (x >= W) break;
            float t =      g0 * __ldg(r + reflect_i(x - 2, W));
            t = fmaf(g1, __ldg(r + reflect_i(x - 1, W)), t);
            t = fmaf(g2, __ldg(r + x), t);
            t = fmaf(g1, __ldg(r + reflect_i(x + 1, W)), t);
            t = fmaf(g0, __ldg(r + reflect_i(x + 2, W)), t);
            out[(size_t)y * S + x] = t;
        }
    }
}

// ---------------------------------------------------------------------------
// 5x5 correlation + 15px border mask. Interior-only nonzero.
__global__ void __launch_bounds__(128) k_conv(const float* __restrict__ img,
                       const float* __restrict__ wp, const float* __restrict__ bp,
                       float* __restrict__ score, int W, int H, int S)
{
    __shared__ float sw[25];
    __shared__ float sb;
    int t = threadIdx.x;
    if (t < 25) sw[t] = __ldg(wp + t);
    if (t == 31) sb = __ldg(bp);
    __syncthreads();

    int y  = blockIdx.y;
    int x0 = (blockIdx.x * 128 + t) * 8;
    if (x0 >= W) return;
    float* orow = score + (size_t)y * S;

    if (y < 15 || y >= H - 15) {
        float4 z = make_float4(0.f, 0.f, 0.f, 0.f);
        if (x0 + 8 <= S) {
            *(float4*)(orow + x0) = z;
            *(float4*)(orow + x0 + 4) = z;
        } else {
            for (int o = 0; o < 8; ++o) if (x0 + o < S) orow[x0 + o] = 0.f;
        }
        return;
    }

    if (x0 >= 8 && x0 + 12 <= W) {
        float acc[8];
        #pragma unroll
        for (int o = 0; o < 8; ++o) acc[o] = sb;
        #pragma unroll
        for (int ky = 0; ky < 5; ++ky) {
            const float4* r4 = (const float4*)(img + (size_t)(y + ky - 2) * S + x0 - 4);
            float4 a0 = __ldg(r4), a1 = __ldg(r4 + 1), a2 = __ldg(r4 + 2), a3 = __ldg(r4 + 3);
            float v[16] = {a0.x,a0.y,a0.z,a0.w, a1.x,a1.y,a1.z,a1.w,
                           a2.x,a2.y,a2.z,a2.w, a3.x,a3.y,a3.z,a3.w};
            #pragma unroll
            for (int kx = 0; kx < 5; ++kx) {
                float w = sw[ky * 5 + kx];
                #pragma unroll
                for (int o = 0; o < 8; ++o) acc[o] = fmaf(w, v[o + kx + 2], acc[o]);
            }
        }
        float4 o0, o1;
        float* p0 = (float*)&o0; float* p1 = (float*)&o1;
        #pragma unroll
        for (int o = 0; o < 4; ++o) {
            int x = x0 + o;
            p0[o] = (x >= 15 && x < W - 15) ? acc[o] : 0.f;
        }
        #pragma unroll
        for (int o = 0; o < 4; ++o) {
            int x = x0 + 4 + o;
            p1[o] = (x >= 15 && x < W - 15) ? acc[o + 4] : 0.f;
        }
        *(float4*)(orow + x0) = o0;
        *(float4*)(orow + x0 + 4) = o1;
    } else {
        for (int o = 0; o < 8; ++o) {
            int x = x0 + o;
            if (x < W) {
                float val = 0.f;
                if (x >= 15 && x < W - 15) {
                    val = sb;
                    for (int ky = 0; ky < 5; ++ky)
                        for (int kx = 0; kx < 5; ++kx)
                            val = fmaf(sw[ky * 5 + kx],
                                       __ldg(img + (size_t)(y + ky - 2) * S + (x + kx - 2)), val);
                }
                orow[x] = val;
            } else if (x < S) orow[x] = 0.f;
        }
    }
}

// ---------------------------------------------------------------------------
// Row max over [x-7,x+7] (clamped). Border rows short-circuit to zeros.
__global__ void __launch_bounds__(128) k_nmsrow(const float* __restrict__ ms,
                                                float* __restrict__ rmax,
                                                int W, int H, int S)
{
    int y  = blockIdx.y;
    int x0 = (blockIdx.x * 128 + threadIdx.x) * 8;
    if (x0 >= W) return;
    float* orow = rmax + (size_t)y * S;

    if (y < 15 || y >= H - 15) {
        float4 z = make_float4(0.f, 0.f, 0.f, 0.f);
        if (x0 + 8 <= S) {
            *(float4*)(orow + x0) = z;
            *(float4*)(orow + x0 + 4) = z;
        } else {
            for (int o = 0; o < 8; ++o) if (x0 + o < S) orow[x0 + o] = 0.f;
        }
        return;
    }

    const float* r = ms + (size_t)y * S;
    if (x0 >= 8 && x0 + 16 <= W) {
        float v[24];
        #pragma unroll
        for (int q = 0; q < 6; ++q) {
            float4 a = __ldg((const float4*)(r + x0 - 8 + q * 4));
            v[q*4] = a.x; v[q*4+1] = a.y; v[q*4+2] = a.z; v[q*4+3] = a.w;
        }
        // window for output o: v[o+1 .. o+15]
        float pre[8];
        float run = v[15];
        #pragma unroll
        for (int j = 14; j >= 1; --j) {
            run = fmaxf(run, v[j]);
            if (j <= 8) pre[j - 1] = run;   // pre[o] = max(v[o+1..15])
        }
        float res[8];
        res[0] = pre[0];
        float run2 = v[16];
        res[1] = fmaxf(pre[1], run2);
        #pragma unroll
        for (int o = 2; o < 8; ++o) {
            run2 = fmaxf(run2, v[o + 15]);
            res[o] = fmaxf(pre[o], run2);
        }
        *(float4*)(orow + x0)     = make_float4(res[0], res[1], res[2], res[3]);
        *(float4*)(orow + x0 + 4) = make_float4(res[4], res[5], res[6], res[7]);
    } else {
        for (int o = 0; o < 8; ++o) {
            int x = x0 + o;
            if (x < W) {
                float m = -1e30f;
                for (int j = -7; j <= 7; ++j) {
                    int xx = x + j;
                    xx = xx < 0 ? 0 : (xx > W - 1 ? W - 1 : xx);
                    m = fmaxf(m, __ldg(r + xx));
                }
                orow[x] = m;
            } else if (x < S) orow[x] = 0.f;
        }
    }
}

// ---------------------------------------------------------------------------
// Column max of rmax over [y-7,y+7] + candidate extraction (4 cols x 8 rows / thread).
// Key: scoreBits<<26 | (5-level)<<23 | (0x7FFFFF - pixIdx)
__global__ void __launch_bounds__(128) k_nmscol(const float* __restrict__ ms,
                                                const float* __restrict__ rmax,
                                                int W, int H, int S, int level)
{
    int x4 = (blockIdx.x * 128 + threadIdx.x) * 4;
    if (x4 >= W) return;
    int y0 = blockIdx.y * 8;

    float4 v[22];
    #pragma unroll
    for (int j = 0; j < 22; ++j) {
        int yy = y0 - 7 + j;
        yy = yy < 0 ? 0 : (yy > H - 1 ? H - 1 : yy);
        v[j] = __ldg((const float4*)(rmax + (size_t)yy * S + x4));
    }
    // window for output o: v[o .. o+14]
    float4 pre[8];
    float4 run = v[14];
    #pragma unroll
    for (int j = 13; j >= 0; --j) {
        run = f4max(run, v[j]);
        if (j <= 7) pre[j] = run;     // pre[o] = max(v[o..14])
    }
    float4 run2 = v[15];
    #pragma unroll
    for (int o = 0; o < 8; ++o) {
        int y = y0 + o;
        if (y >= H) break;
        float4 m;
        if (o == 0) m = pre[0];
        else {
            if (o >= 2) run2 = f4max(run2, v[o + 14]);
            m = f4max(pre[o], run2);
        }
        float4 s4 = __ldg((const float4*)(ms + (size_t)y * S + x4));
        const float* sp = (const float*)&s4;
        const float* mp = (const float*)&m;
        #pragma unroll
        for (int cc = 0; cc < 4; ++cc) {
            int x = x4 + cc;
            float s = sp[cc];
            if (x < W && s > 0.0f && s == mp[cc]) {
                unsigned sbits = __float_as_uint(s) | 0x80000000u;
                int pix = y * W + x;
                u64 key = ((u64)sbits << 26) | ((u64)(5 - level) << 23)
                        | (u64)(0x7FFFFF - pix);
                int pos = atomicAdd(&g_cnt[level], 1);
                if (pos < CAP) g_cand[(size_t)level * CAP + pos] = key;
            }
        }
    }
}

// ---------------------------------------------------------------------------
// All 6 per-level radix selects concurrently: block l selects top c_k[l] of
// level l's candidates and appends them to the pool.
__global__ void __launch_bounds__(1024) k_select6()
{
    __shared__ int hist[256];
    __shared__ u64 s_pref;
    __shared__ int s_k;
    int l   = blockIdx.x;
    int tid = threadIdx.x;
    const u64* src = g_cand + (size_t)l * CAP;
    int k   = c_k[l];
    int cnt = g_cnt[l];
    if (cnt > CAP) cnt = CAP;
    u64 thr = 0;
    if (cnt > k) {
        if (tid == 0) { s_pref = 0ull; s_k = k; }
        __syncthreads();
        for (int b = 7; b >= 0; --b) {
            if (tid < 256) hist[tid] = 0;
            __syncthreads();
            u64 pref = s_pref;
            u64 maskHi = (b == 7) ? 0ull : (~0ull << (8 * (b + 1)));
            for (int i = tid; i < cnt; i += 1024) {
                u64 key = src[i];
                if ((key & maskHi) == pref)
                    atomicAdd(&hist[(int)((key >> (8 * b)) & 255)], 1);
            }
            __syncthreads();
            if (tid == 0) {
                int kk = s_k, cum = 0, d = 255;
                for (; d >= 0; --d) { cum += hist[d]; if (cum >= kk) break; }
                s_k = kk - (cum - hist[d]);
                s_pref = s_pref | ((u64)d << (8 * b));
            }
            __syncthreads();
        }
        thr = s_pref;
    }
    __syncthreads();
    for (int i = tid; i < cnt; i += 1024) {
        u64 key = src[i];
        if (key >= thr) {
            int p = atomicAdd(&g_cnt[6], 1);
            g_pool[p] = key;
        }
    }
}

// ---------------------------------------------------------------------------
// Final: radix-select top 2048 of pool -> smem, bitonic sort, decode, emit.
__global__ void __launch_bounds__(1024) k_final(float* __restrict__ out, int out_size)
{
    __shared__ int hist[256];
    __shared__ u64 s_pref;
    __shared__ int s_k, s_cnt;
    __shared__ u64 s[2048];
    int tid = threadIdx.x;
    int cnt = g_cnt[6];
    if (cnt > 12288) cnt = 12288;

    u64 thr = 0;
    if (cnt > 2048) {
        if (tid == 0) { s_pref = 0ull; s_k = 2048; }
        __syncthreads();
        for (int b = 7; b >= 0; --b) {
            if (tid < 256) hist[tid] = 0;
            __syncthreads();
            u64 pref = s_pref;
            u64 maskHi = (b == 7) ? 0ull : (~0ull << (8 * (b + 1)));
            for (int i = tid; i < cnt; i += 1024) {
                u64 key = g_pool[i];
                if ((key & maskHi) == pref)
                    atomicAdd(&hist[(int)((key >> (8 * b)) & 255)], 1);
            }
            __syncthreads();
            if (tid == 0) {
                int kk = s_k, cum = 0, d = 255;
                for (; d >= 0; --d) { cum += hist[d]; if (cum >= kk) break; }
                s_k = kk - (cum - hist[d]);
                s_pref = s_pref | ((u64)d << (8 * b));
            }
            __syncthreads();
        }
        thr = s_pref;
    }
    s[tid] = 0ull; s[tid + 1024] = 0ull;
    if (tid == 0) s_cnt = 0;
    __syncthreads();
    for (int i = tid; i < cnt; i += 1024) {
        u64 key = g_pool[i];
        if (key >= thr) {
            int p = atomicAdd(&s_cnt, 1);
            if (p < 2048) s[p] = key;
        }
    }
    __syncthreads();

    // bitonic sort ascending
    for (int ksz = 2; ksz <= 2048; ksz <<= 1) {
        for (int j = ksz >> 1; j > 0; j >>= 1) {
            #pragma unroll
            for (int half = 0; half < 2; ++half) {
                int i = tid + half * 1024;
                int ixj = i ^ j;
                if (ixj > i) {
                    u64 a = s[i], b = s[ixj];
                    bool asc = ((i & ksz) == 0);
                    if (asc ? (a > b) : (a < b)) { s[i] = b; s[ixj] = a; }
                }
            }
            __syncthreads();
        }
    }

    bool haveL = (out_size >= 12288);
    bool haveR = (out_size >= 14336) || (out_size < 12288);
    int rbase  = (out_size >= 14336) ? 12288 : 0;
    for (int r = tid; r < 2048; r += 1024) {
        u64 key = s[2047 - r];
        int pix = 0x7FFFFF - (int)(key & 0x7FFFFF);
        int lvl = 5 - (int)((key >> 23) & 7);
        float sc = __uint_as_float((unsigned)(key >> 26) & 0x7FFFFFFFu);
        int Wl = c_W[lvl];
        int py = pix / Wl, px = pix - py * Wl;
        float f  = c_fact[lvl], sg = c_scal[lvl];
        float fx = __fmul_rn((float)px, f);
        float fy = __fmul_rn((float)py, f);
        if (haveL) {
            float* L = out + (size_t)r * 6;
            L[0] = sg; L[1] = 0.f; L[2] = fx;
            L[3] = 0.f; L[4] = sg; L[5] = fy;
        }
        if (haveR) out[rbase + r] = sc;
    }
}

// ---------------------------------------------------------------------------
extern "C" void kernel_launch(void* const* d_in, const int* in_sizes, int n_in,
                              void* d_out, int out_size)
{
    const float* img = (const float*)d_in[0];
    const float* cw  = (const float*)d_in[1];
    const float* cb  = (const float*)d_in[2];
    float* out = (float*)d_out;

    void *p_up, *p_i2, *p_i3, *p_i4, *p_i5, *p_bA, *p_bB, *p_sc, *p_rm;
    cudaGetSymbolAddress(&p_up, g_imgup);
    cudaGetSymbolAddress(&p_i2, g_img2);
    cudaGetSymbolAddress(&p_i3, g_img3);
    cudaGetSymbolAddress(&p_i4, g_img4);
    cudaGetSymbolAddress(&p_i5, g_img5);
    cudaGetSymbolAddress(&p_bA, g_blurA);
    cudaGetSymbolAddress(&p_bB, g_blurB);
    cudaGetSymbolAddress(&p_sc, g_score);
    cudaGetSymbolAddress(&p_rm, g_rmax);
    float *imgup=(float*)p_up, *img2=(float*)p_i2, *img3=(float*)p_i3,
          *img4=(float*)p_i4, *img5=(float*)p_i5, *bA=(float*)p_bA, *bB=(float*)p_bB,
          *sc=(float*)p_sc, *rm=(float*)p_rm;

    // gaussian 5-tap, sigma=1 (same host math as the passing R2 kernel)
    float gx[5] = {4.f, 1.f, 0.f, 1.f, 4.f};
    float g[5], gs = 0.f;
    for (int i = 0; i < 5; ++i) { g[i] = expf(-gx[i] * 0.5f); gs += g[i]; }
    for (int i = 0; i < 5; ++i) g[i] /= gs;

    const int Ws[6] = {2896, 2048, 1448, 1023, 723, 511};  // true widths
    const int Ss[6] = {2896, 2048, 1448, 1024, 724, 512};  // padded strides
    const float* lvlImg[6];
    lvlImg[0] = imgup; lvlImg[1] = img; lvlImg[2] = img2;
    lvlImg[3] = img3;  lvlImg[4] = img4; lvlImg[5] = img5;

    k_zero<<<1, 32>>>();

    // level 0: upscale 2048 -> 2896
    {
        dim3 gr((2896 + 255) / 256, 2896);
        k_resize<<<gr, 256>>>(img, 2048, 2048, 2048, imgup, 2896, 2896,
                              (float)(2048.0 / 2896.0));
    }
    // pyrdown chain: level i+1 -> level i+2
    {
        float* dsts[4] = {img2, img3, img4, img5};
        const float* src = img;
        for (int i = 0; i < 4; ++i) {
            int sw = Ws[i + 1], sS = Ss[i + 1];
            int dw = Ws[i + 2], dS = Ss[i + 2];
            dim3 gb((sw + 511) / 512, sw);
            k_blurV<<<gb, 128>>>(src, bA, sS, sw, sw, g[0], g[1], g[2]);
            k_blurH<<<gb, 128>>>(bA, bB, sS, sw, sw, g[0], g[1], g[2]);
            dim3 gr((dw + 255) / 256, dw);
            k_resize<<<gr, 256>>>(bB, sS, sw, sw, dsts[i], dS, dw,
                                  (float)((double)sw / (double)dw));
            src = dsts[i];
        }
    }
    // detection on all levels
    for (int l = 0; l < 6; ++l) {
        int W = Ws[l], S = Ss[l];
        dim3 g2((W + 1023) / 1024, W);
        k_conv  <<<g2, 128>>>(lvlImg[l], cw, cb, sc, W, W, S);
        k_nmsrow<<<g2, 128>>>(sc, rm, W, W, S);
        dim3 gc((W + 511) / 512, (W + 7) / 8);
        k_nmscol<<<gc, 128>>>(sc, rm, W, W, S, l);
    }
    // selection
    k_select6<<<6, 1024>>>();
    k_final<<<1, 1024>>>(out, out_size);
}

// round 5
// speedup vs baseline: 1.8333x; 1.2036x over previous
#include <cuda_runtime.h>
#include <math.h>
#include <stdint.h>

typedef unsigned long long u64;

#define CAP 65536

// ---- device scratch (no allocations allowed) ----
__device__ float g_imgup[2896*2896];
__device__ float g_img2 [1448*1448];
__device__ float g_img3 [1024*1023];
__device__ float g_img4 [724*723];
__device__ float g_img5 [512*511];
__device__ float g_blurB[2048*2048];
__device__ float g_score[16510464];
__device__ float g_rmax [16510464];
__device__ u64   g_cand[6*CAP];
__device__ u64   g_pool[12288];
__device__ int   g_cnt[8];   // [0..5]=per-level cand count, [6]=pool

__constant__ int   c_W[6]    = {2896,2048,1448,1023,723,511};
__constant__ int   c_S[6]    = {2896,2048,1448,1024,724,512};
__constant__ int   c_off[6]  = {0, 8386816, 12581120, 14677824, 15725376, 16248828};
__constant__ float c_fact[6] = {(float)(2048.0/2896.0), 1.0f, (float)(2048.0/1448.0),
                                (float)(2048.0/1023.0), (float)(2048.0/723.0), (float)(2048.0/511.0)};
__constant__ float c_scal[6] = {(float)(2048.0/2896.0*22.0), 22.0f, (float)(2048.0/1448.0*22.0),
                                (float)(2048.0/1023.0*22.0), (float)(2048.0/723.0*22.0), (float)(2048.0/511.0*22.0)};
__constant__ int   c_k[6]    = {1040,1560,1820,1950,2015,2047};

// conv+nms merged-grid tables: blocks/level = W rows x tilesX (tile=1008 px out)
__constant__ int c_cumCN[6] = {0, 8688, 14832, 17728, 19774, 20497}; // total 21008
__constant__ int c_tX[6]    = {3, 3, 2, 2, 1, 1};
// nmscol merged-grid tables: blocks/level = ceil(W/8) x ceil(W/512)
__constant__ int c_cumNC[6] = {0, 2172, 3196, 3739, 3995, 4177};     // total 4241
__constant__ int c_bx[6]    = {6, 4, 3, 2, 2, 1};

__device__ __forceinline__ float4 f4max(float4 a, float4 b)
{
    return make_float4(fmaxf(a.x,b.x), fmaxf(a.y,b.y), fmaxf(a.z,b.z), fmaxf(a.w,b.w));
}

__global__ void k_zero()
{
    if (threadIdx.x < 8) g_cnt[threadIdx.x] = 0;
}

// ---------------------------------------------------------------------------
// jax.image.resize bilinear, antialias=False.
__global__ void __launch_bounds__(256) k_resize(const float* __restrict__ in, int sIn,
                         int sw, int sh, float* __restrict__ dst, int sOut, int dw,
                         float invs)
{
    int dx = blockIdx.x * 256 + threadIdx.x;
    int dy = blockIdx.y;
    if (dx >= dw) return;

    float sy = __fadd_rn(__fmul_rn(__fadd_rn((float)dy, 0.5f), invs), -0.5f);
    float sx = __fadd_rn(__fmul_rn(__fadd_rn((float)dx, 0.5f), invs), -0.5f);
    int jy0 = (int)floorf(sy), jy1 = jy0 + 1;
    int jx0 = (int)floorf(sx), jx1 = jx0 + 1;
    float wy0 = __fadd_rn(1.0f, -__fadd_rn(sy, -(float)jy0));
    float wy1 = __fadd_rn(1.0f, -__fadd_rn((float)jy1, -sy));
    float wx0 = __fadd_rn(1.0f, -__fadd_rn(sx, -(float)jx0));
    float wx1 = __fadd_rn(1.0f, -__fadd_rn((float)jx1, -sx));
    bool vy0 = (jy0 >= 0), vy1 = (jy1 <= sh - 1);
    bool vx0 = (jx0 >= 0), vx1 = (jx1 <= sw - 1);
    int cy0 = vy0 ? jy0 : 0, cy1 = vy1 ? jy1 : sh - 1;
    int cx0 = vx0 ? jx0 : 0, cx1 = vx1 ? jx1 : sw - 1;

    float p00 = __ldg(in + (size_t)cy0 * sIn + cx0);
    float p01 = __ldg(in + (size_t)cy0 * sIn + cx1);
    float p10 = __ldg(in + (size_t)cy1 * sIn + cx0);
    float p11 = __ldg(in + (size_t)cy1 * sIn + cx1);

    float c0, c1;
    if (vy0 && vy1) {
        float tot = __fadd_rn(wy0, wy1);
        float n0 = __fdiv_rn(wy0, tot), n1 = __fdiv_rn(wy1, tot);
        c0 = __fadd_rn(__fmul_rn(n0, p00), __fmul_rn(n1, p10));
        c1 = __fadd_rn(__fmul_rn(n0, p01), __fmul_rn(n1, p11));
    } else if (vy0) { c0 = p00; c1 = p01; }
    else            { c0 = p10; c1 = p11; }

    float v;
    if (vx0 && vx1) {
        float tot = __fadd_rn(wx0, wx1);
        float n0 = __fdiv_rn(wx0, tot), n1 = __fdiv_rn(wx1, tot);
        v = __fadd_rn(__fmul_rn(n0, c0), __fmul_rn(n1, c1));
    } else if (vx0) v = c0; else v = c1;

    dst[(size_t)dy * sOut + dx] = v;
}

// ---------------------------------------------------------------------------
__device__ __forceinline__ int reflect_i(int i, int n)
{
    if (i < 0) return -i;
    if (i >= n) return 2 * n - 2 - i;
    return i;
}

// Fused separable 5-tap gaussian blur (reflect): V in registers, H via smem.
// Output tile 504x8, block 128 threads (4 px wide each).
__global__ void __launch_bounds__(128) k_blurVH(const float* __restrict__ in,
        float* __restrict__ out, int S, int W, int H,
        float g0, float g1, float g2)
{
    __shared__ float sv[8][512];
    int t  = threadIdx.x;
    int xb = blockIdx.x * 504;
    int yb = blockIdx.y * 8;
    int xg = xb - 4 + t * 4;

    float4 raw[12];
    bool fast = (xg >= 0) && (xg + 4 <= W);
    #pragma unroll
    for (int r = 0; r < 12; ++r) {
        const float* rowp = in + (size_t)reflect_i(yb - 2 + r, H) * S;
        if (fast) {
            raw[r] = __ldg((const float4*)(rowp + xg));
        } else {
            float t0 = __ldg(rowp + reflect_i(xg,     W));
            float t1 = __ldg(rowp + reflect_i(xg + 1, W));
            float t2 = __ldg(rowp + reflect_i(xg + 2, W));
            float t3 = __ldg(rowp + reflect_i(xg + 3, W));
            raw[r] = make_float4(t0, t1, t2, t3);
        }
    }
    #pragma unroll
    for (int r = 0; r < 8; ++r) {
        float4 a = raw[r], b = raw[r+1], c = raw[r+2], d = raw[r+3], e = raw[r+4];
        float4 vb;
        vb.x = fmaf(g0, e.x, fmaf(g1, d.x, fmaf(g2, c.x, fmaf(g1, b.x, g0 * a.x))));
        vb.y = fmaf(g0, e.y, fmaf(g1, d.y, fmaf(g2, c.y, fmaf(g1, b.y, g0 * a.y))));
        vb.z = fmaf(g0, e.z, fmaf(g1, d.z, fmaf(g2, c.z, fmaf(g1, b.z, g0 * a.z))));
        vb.w = fmaf(g0, e.w, fmaf(g1, d.w, fmaf(g2, c.w, fmaf(g1, b.w, g0 * a.w))));
        *(float4*)&sv[r][t * 4] = vb;
    }
    __syncthreads();
    if (t >= 126) return;
    int xo = xb + t * 4;
    if (xo >= W) return;
    #pragma unroll
    for (int r = 0; r < 8; ++r) {
        int yo = yb + r;
        if (yo >= H) break;
        float v[12];
        #pragma unroll
        for (int q = 0; q < 3; ++q) {
            float4 a = *(float4*)&sv[r][t * 4 + q * 4];
            v[q*4] = a.x; v[q*4+1] = a.y; v[q*4+2] = a.z; v[q*4+3] = a.w;
        }
        float res[4];
        #pragma unroll
        for (int c = 0; c < 4; ++c) {
            res[c] = fmaf(g0, v[c + 6], fmaf(g1, v[c + 5],
                     fmaf(g2, v[c + 4], fmaf(g1, v[c + 3], g0 * v[c + 2]))));
        }
        float* orow = out + (size_t)yo * S;
        if (xo + 4 <= W) {
            *(float4*)(orow + xo) = make_float4(res[0], res[1], res[2], res[3]);
        } else {
            for (int c = 0; c < 4; ++c) if (xo + c < W) orow[xo + c] = res[c];
        }
    }
}

// ---------------------------------------------------------------------------
// Merged (all 6 levels) fused 5x5-conv + border-mask + row-max.
// Per block: one row, one 1008-px output tile; conv for [ob-8, ob+1016) into smem.
__global__ void __launch_bounds__(128) k_convnms(const float* __restrict__ imgOrig,
        const float* __restrict__ wp, const float* __restrict__ bp)
{
    __shared__ float swt[25];
    __shared__ float sb;
    __shared__ float sc[1024];
    int t = threadIdx.x;
    if (t < 25) swt[t] = __ldg(wp + t);
    if (t == 31) sb = __ldg(bp);

    int bid = blockIdx.x;
    int l = 5;
    while (bid < c_cumCN[l]) --l;
    int rem  = bid - c_cumCN[l];
    int tx   = c_tX[l];
    int y    = rem / tx;
    int tile = rem - y * tx;
    int W = c_W[l], H = W, S = c_S[l];
    const float* img;
    switch (l) {
        case 0: img = g_imgup; break;
        case 1: img = imgOrig; break;
        case 2: img = g_img2;  break;
        case 3: img = g_img3;  break;
        case 4: img = g_img4;  break;
        default: img = g_img5; break;
    }
    float* srow = g_score + c_off[l] + (size_t)y * S;
    float* rrow = g_rmax  + c_off[l] + (size_t)y * S;
    int ob  = tile * 1008;
    int xc0 = ob - 8 + t * 8;

    if (y < 15 || y >= H - 15) {
        float4 z = make_float4(0.f, 0.f, 0.f, 0.f);
        if (xc0 >= 0 && xc0 + 8 <= W) {
            *(float4*)(srow + xc0) = z; *(float4*)(srow + xc0 + 4) = z;
        } else {
            for (int o = 0; o < 8; ++o) {
                int x = xc0 + o;
                if (x >= 0 && x < W) srow[x] = 0.f;
            }
        }
        if (t < 126) {
            int xr0 = ob + t * 8;
            if (xr0 + 8 <= W) {
                *(float4*)(rrow + xr0) = z; *(float4*)(rrow + xr0 + 4) = z;
            } else {
                for (int o = 0; o < 8; ++o) if (xr0 + o < W) rrow[xr0 + o] = 0.f;
            }
        }
        return;
    }
    __syncthreads();

    float cv[8];
    if (xc0 >= 15 && xc0 + 23 <= W) {
        #pragma unroll
        for (int o = 0; o < 8; ++o) cv[o] = sb;
        #pragma unroll
        for (int ky = 0; ky < 5; ++ky) {
            const float4* r4 = (const float4*)(img + (size_t)(y + ky - 2) * S + xc0 - 4);
            float4 a0 = __ldg(r4), a1 = __ldg(r4+1), a2 = __ldg(r4+2), a3 = __ldg(r4+3);
            float v[16] = {a0.x,a0.y,a0.z,a0.w, a1.x,a1.y,a1.z,a1.w,
                           a2.x,a2.y,a2.z,a2.w, a3.x,a3.y,a3.z,a3.w};
            #pragma unroll
            for (int kx = 0; kx < 5; ++kx) {
                float w = swt[ky * 5 + kx];
                #pragma unroll
                for (int o = 0; o < 8; ++o) cv[o] = fmaf(w, v[o + kx + 2], cv[o]);
            }
        }
    } else {
        for (int o = 0; o < 8; ++o) {
            int x = xc0 + o;
            float val = 0.f;
            if (x >= 15 && x < W - 15) {
                val = sb;
                for (int ky = 0; ky < 5; ++ky)
                    for (int kx = 0; kx < 5; ++kx)
                        val = fmaf(swt[ky * 5 + kx],
                                   __ldg(img + (size_t)(y + ky - 2) * S + (x + kx - 2)), val);
            }
            cv[o] = val;
        }
    }
    #pragma unroll
    for (int o = 0; o < 8; ++o) sc[t * 8 + o] = cv[o];

    // store score
    if (xc0 >= 0 && xc0 + 8 <= W) {
        *(float4*)(srow + xc0)     = make_float4(cv[0], cv[1], cv[2], cv[3]);
        *(float4*)(srow + xc0 + 4) = make_float4(cv[4], cv[5], cv[6], cv[7]);
    } else {
        for (int o = 0; o < 8; ++o) {
            int x = xc0 + o;
            if (x >= 0 && x < W) srow[x] = cv[o];
        }
    }
    __syncthreads();

    if (t >= 126) return;
    int xr0 = ob + t * 8;
    if (xr0 >= W) return;
    float v[22];
    #pragma unroll
    for (int j = 0; j < 22; ++j) v[j] = sc[t * 8 + 1 + j];
    float pre[8];
    float run = v[14];
    #pragma unroll
    for (int j = 14; j >= 0; --j) {
        run = fmaxf(run, v[j]);
        if (j <= 7) pre[j] = run;
    }
    float res[8];
    res[0] = pre[0];
    float run2 = v[15];
    res[1] = fmaxf(pre[1], run2);
    #pragma unroll
    for (int o = 2; o < 8; ++o) {
        run2 = fmaxf(run2, v[o + 14]);
        res[o] = fmaxf(pre[o], run2);
    }
    if (xr0 + 8 <= W) {
        *(float4*)(rrow + xr0)     = make_float4(res[0], res[1], res[2], res[3]);
        *(float4*)(rrow + xr0 + 4) = make_float4(res[4], res[5], res[6], res[7]);
    } else {
        for (int o = 0; o < 8; ++o) if (xr0 + o < W) rrow[xr0 + o] = res[o];
    }
}

// ---------------------------------------------------------------------------
// Merged (all levels) column-max + candidate extraction (4 cols x 8 rows/thread).
__global__ void __launch_bounds__(128) k_nmscolAll()
{
    int bid = blockIdx.x;
    int l = 5;
    while (bid < c_cumNC[l]) --l;
    int rem  = bid - c_cumNC[l];
    int bx   = c_bx[l];
    int yblk = rem / bx;
    int xblk = rem - yblk * bx;
    int W = c_W[l], H = W, S = c_S[l];
    const float* ms   = g_score + c_off[l];
    const float* rmax = g_rmax  + c_off[l];

    int x4 = xblk * 512 + threadIdx.x * 4;
    if (x4 >= W) return;
    int y0 = yblk * 8;

    float4 v[22];
    #pragma unroll
    for (int j = 0; j < 22; ++j) {
        int yy = y0 - 7 + j;
        yy = yy < 0 ? 0 : (yy > H - 1 ? H - 1 : yy);
        v[j] = __ldg((const float4*)(rmax + (size_t)yy * S + x4));
    }
    float4 pre[8];
    float4 run = v[14];
    #pragma unroll
    for (int j = 13; j >= 0; --j) {
        run = f4max(run, v[j]);
        if (j <= 7) pre[j] = run;
    }
    float4 run2 = v[15];
    #pragma unroll
    for (int o = 0; o < 8; ++o) {
        int y = y0 + o;
        if (y >= H) break;
        float4 m;
        if (o == 0) m = pre[0];
        else {
            if (o >= 2) run2 = f4max(run2, v[o + 14]);
            m = f4max(pre[o], run2);
        }
        float4 s4 = __ldg((const float4*)(ms + (size_t)y * S + x4));
        const float* sp = (const float*)&s4;
        const float* mp = (const float*)&m;
        #pragma unroll
        for (int cc = 0; cc < 4; ++cc) {
            int x = x4 + cc;
            float s = sp[cc];
            if (x < W && s > 0.0f && s == mp[cc]) {
                unsigned sbits = __float_as_uint(s) | 0x80000000u;
                int pix = y * W + x;
                u64 key = ((u64)sbits << 26) | ((u64)(5 - l) << 23)
                        | (u64)(0x7FFFFF - pix);
                int pos = atomicAdd(&g_cnt[l], 1);
                if (pos < CAP) g_cand[(size_t)l * CAP + pos] = key;
            }
        }
    }
}

// ---------------------------------------------------------------------------
// All 6 per-level radix selects concurrently (block l -> level l).
__global__ void __launch_bounds__(1024) k_select6()
{
    __shared__ int hist[256];
    __shared__ u64 s_pref;
    __shared__ int s_k;
    int l   = blockIdx.x;
    int tid = threadIdx.x;
    const u64* src = g_cand + (size_t)l * CAP;
    int k   = c_k[l];
    int cnt = g_cnt[l];
    if (cnt > CAP) cnt = CAP;
    u64 thr = 0;
    if (cnt > k) {
        if (tid == 0) { s_pref = 0ull; s_k = k; }
        __syncthreads();
        for (int b = 7; b >= 0; --b) {
            if (tid < 256) hist[tid] = 0;
            __syncthreads();
            u64 pref = s_pref;
            u64 maskHi = (b == 7) ? 0ull : (~0ull << (8 * (b + 1)));
            for (int i = tid; i < cnt; i += 1024) {
                u64 key = src[i];
                if ((key & maskHi) == pref)
                    atomicAdd(&hist[(int)((key >> (8 * b)) & 255)], 1);
            }
            __syncthreads();
            if (tid == 0) {
                int kk = s_k, cum = 0, d = 255;
                for (; d >= 0; --d) { cum += hist[d]; if (cum >= kk) break; }
                s_k = kk - (cum - hist[d]);
                s_pref = s_pref | ((u64)d << (8 * b));
            }
            __syncthreads();
        }
        thr = s_pref;
    }
    __syncthreads();
    for (int i = tid; i < cnt; i += 1024) {
        u64 key = src[i];
        if (key >= thr) {
            int p = atomicAdd(&g_cnt[6], 1);
            g_pool[p] = key;
        }
    }
}

// ---------------------------------------------------------------------------
// Final: radix-select top 2048 -> smem, bitonic sort, decode, emit.
__global__ void __launch_bounds__(1024) k_final(float* __restrict__ out, int out_size)
{
    __shared__ int hist[256];
    __shared__ u64 s_pref;
    __shared__ int s_k, s_cnt;
    __shared__ u64 s[2048];
    int tid = threadIdx.x;
    int cnt = g_cnt[6];
    if (cnt > 12288) cnt = 12288;

    u64 thr = 0;
    if (cnt > 2048) {
        if (tid == 0) { s_pref = 0ull; s_k = 2048; }
        __syncthreads();
        for (int b = 7; b >= 0; --b) {
            if (tid < 256) hist[tid] = 0;
            __syncthreads();
            u64 pref = s_pref;
            u64 maskHi = (b == 7) ? 0ull : (~0ull << (8 * (b + 1)));
            for (int i = tid; i < cnt; i += 1024) {
                u64 key = g_pool[i];
                if ((key & maskHi) == pref)
                    atomicAdd(&hist[(int)((key >> (8 * b)) & 255)], 1);
            }
            __syncthreads();
            if (tid == 0) {
                int kk = s_k, cum = 0, d = 255;
                for (; d >= 0; --d) { cum += hist[d]; if (cum >= kk) break; }
                s_k = kk - (cum - hist[d]);
                s_pref = s_pref | ((u64)d << (8 * b));
            }
            __syncthreads();
        }
        thr = s_pref;
    }
    s[tid] = 0ull; s[tid + 1024] = 0ull;
    if (tid == 0) s_cnt = 0;
    __syncthreads();
    for (int i = tid; i < cnt; i += 1024) {
        u64 key = g_pool[i];
        if (key >= thr) {
            int p = atomicAdd(&s_cnt, 1);
            if (p < 2048) s[p] = key;
        }
    }
    __syncthreads();

    for (int ksz = 2; ksz <= 2048; ksz <<= 1) {
        for (int j = ksz >> 1; j > 0; j >>= 1) {
            #pragma unroll
            for (int half = 0; half < 2; ++half) {
                int i = tid + half * 1024;
                int ixj = i ^ j;
                if (ixj > i) {
                    u64 a = s[i], b = s[ixj];
                    bool asc = ((i & ksz) == 0);
                    if (asc ? (a > b) : (a < b)) { s[i] = b; s[ixj] = a; }
                }
            }
            __syncthreads();
        }
    }

    bool haveL = (out_size >= 12288);
    bool haveR = (out_size >= 14336) || (out_size < 12288);
    int rbase  = (out_size >= 14336) ? 12288 : 0;
    for (int r = tid; r < 2048; r += 1024) {
        u64 key = s[2047 - r];
        int pix = 0x7FFFFF - (int)(key & 0x7FFFFF);
        int lvl = 5 - (int)((key >> 23) & 7);
        float scv = __uint_as_float((unsigned)(key >> 26) & 0x7FFFFFFFu);
        int Wl = c_W[lvl];
        int py = pix / Wl, px = pix - py * Wl;
        float f  = c_fact[lvl], sg = c_scal[lvl];
        float fx = __fmul_rn((float)px, f);
        float fy = __fmul_rn((float)py, f);
        if (haveL) {
            float* L = out + (size_t)r * 6;
            L[0] = sg; L[1] = 0.f; L[2] = fx;
            L[3] = 0.f; L[4] = sg; L[5] = fy;
        }
        if (haveR) out[rbase + r] = scv;
    }
}

// ---------------------------------------------------------------------------
extern "C" void kernel_launch(void* const* d_in, const int* in_sizes, int n_in,
                              void* d_out, int out_size)
{
    const float* img = (const float*)d_in[0];
    const float* cw  = (const float*)d_in[1];
    const float* cb  = (const float*)d_in[2];
    float* out = (float*)d_out;

    void *p_up, *p_i2, *p_i3, *p_i4, *p_i5, *p_bB;
    cudaGetSymbolAddress(&p_up, g_imgup);
    cudaGetSymbolAddress(&p_i2, g_img2);
    cudaGetSymbolAddress(&p_i3, g_img3);
    cudaGetSymbolAddress(&p_i4, g_img4);
    cudaGetSymbolAddress(&p_i5, g_img5);
    cudaGetSymbolAddress(&p_bB, g_blurB);
    float *imgup=(float*)p_up, *img2=(float*)p_i2, *img3=(float*)p_i3,
          *img4=(float*)p_i4, *img5=(float*)p_i5, *bB=(float*)p_bB;

    // gaussian 5-tap, sigma=1 (identical host math to the passing kernels)
    float gx[5] = {4.f, 1.f, 0.f, 1.f, 4.f};
    float g[5], gs = 0.f;
    for (int i = 0; i < 5; ++i) { g[i] = expf(-gx[i] * 0.5f); gs += g[i]; }
    for (int i = 0; i < 5; ++i) g[i] /= gs;

    const int Ws[6] = {2896, 2048, 1448, 1023, 723, 511};
    const int Ss[6] = {2896, 2048, 1448, 1024, 724, 512};

    k_zero<<<1, 32>>>();

    // level 0: upscale 2048 -> 2896
    {
        dim3 gr((2896 + 255) / 256, 2896);
        k_resize<<<gr, 256>>>(img, 2048, 2048, 2048, imgup, 2896, 2896,
                              (float)(2048.0 / 2896.0));
    }
    // pyrdown chain (fused blur, then resize)
    {
        float* dsts[4] = {img2, img3, img4, img5};
        const float* src = img;
        for (int i = 0; i < 4; ++i) {
            int sw = Ws[i + 1], sS = Ss[i + 1];
            int dw = Ws[i + 2], dS = Ss[i + 2];
            dim3 gb((sw + 503) / 504, (sw + 7) / 8);
            k_blurVH<<<gb, 128>>>(src, bB, sS, sw, sw, g[0], g[1], g[2]);
            dim3 gr((dw + 255) / 256, dw);
            k_resize<<<gr, 256>>>(bB, sS, sw, sw, dsts[i], dS, dw,
                                  (float)((double)sw / (double)dw));
            src = dsts[i];
        }
    }
    // merged detection across all 6 levels
    k_convnms  <<<21008, 128>>>(img, cw, cb);
    k_nmscolAll<<<4241, 128>>>();
    // selection
    k_select6<<<6, 1024>>>();
    k_final<<<1, 1024>>>(out, out_size);
}

// round 7
// speedup vs baseline: 1.8429x; 1.0052x over previous
#include <cuda_runtime.h>
#include <math.h>
#include <stdint.h>

typedef unsigned long long u64;

#define CAP 65536

// ---- device scratch (no allocations allowed) ----
__device__ float    g_imgup[2896*2896];
__device__ float    g_img2 [1448*1448];
__device__ float    g_img3 [1024*1023];
__device__ float    g_img4 [724*723];
__device__ float    g_img5 [512*511];
__device__ float    g_blurB[2048*2048];
__device__ float    g_rmax [16510464];
__device__ unsigned g_mask [518784];
__device__ float4   g_rtab [6601];
__device__ u64      g_cand[6*CAP];
__device__ u64      g_pool[12288];
__device__ int      g_cnt[8];   // [0..5]=per-level cand count, [6]=pool

__constant__ int   c_W[6]    = {2896,2048,1448,1023,723,511};
__constant__ int   c_S[6]    = {2896,2048,1448,1024,724,512};
__constant__ int   c_off[6]  = {0, 8386816, 12581120, 14677824, 15725376, 16248832};
__constant__ int   c_mS[6]   = {91,64,46,32,23,16};
__constant__ int   c_moff[6] = {0, 263536, 394608, 461216, 493952, 510581};
__constant__ float c_fact[6] = {(float)(2048.0/2896.0), 1.0f, (float)(2048.0/1448.0),
                                (float)(2048.0/1023.0), (float)(2048.0/723.0), (float)(2048.0/511.0)};
__constant__ float c_scal[6] = {(float)(2048.0/2896.0*22.0), 22.0f, (float)(2048.0/1448.0*22.0),
                                (float)(2048.0/1023.0*22.0), (float)(2048.0/723.0*22.0), (float)(2048.0/511.0*22.0)};
__constant__ int   c_k[6]    = {1040,1560,1820,1950,2015,2047};

// tile tables: blocks/level = ceil(W/512) x ceil(W/8)  (shared by convnms & colcheck)
__constant__ int c_cumNC[6] = {0, 2172, 3196, 3739, 3995, 4177};   // total 4241
__constant__ int c_bx[6]    = {6, 4, 3, 2, 2, 1};

// resize-weight-table layout
__constant__ int   c_toff[5] = {0, 2896, 4344, 5367, 6090};        // total 6601
__constant__ int   c_rsw[5]  = {2048, 2048, 1448, 1023, 723};
__constant__ float c_rinv[5] = {(float)(2048.0/2896.0), (float)(2048.0/1448.0),
                                (float)(1448.0/1023.0), (float)(1023.0/723.0),
                                (float)(723.0/511.0)};

__device__ __forceinline__ float4 f4max(float4 a, float4 b)
{
    return make_float4(fmaxf(a.x,b.x), fmaxf(a.y,b.y), fmaxf(a.z,b.z), fmaxf(a.w,b.w));
}

// ---------------------------------------------------------------------------
// init: zero counters + build resize weight tables (bit-identical arithmetic
// to the former per-pixel resize math).
__global__ void __launch_bounds__(256) k_init()
{
    int idx = blockIdx.x * 256 + threadIdx.x;
    if (idx < 8) g_cnt[idx] = 0;
    if (idx >= 6601) return;
    int r = 4;
    while (idx < c_toff[r]) --r;
    int d  = idx - c_toff[r];
    int sw = c_rsw[r];
    float invs = c_rinv[r];

    float sx = __fadd_rn(__fmul_rn(__fadd_rn((float)d, 0.5f), invs), -0.5f);
    int j0 = (int)floorf(sx), j1 = j0 + 1;
    float w0 = __fadd_rn(1.0f, -__fadd_rn(sx, -(float)j0));
    float w1 = __fadd_rn(1.0f, -__fadd_rn((float)j1, -sx));
    bool v0 = (j0 >= 0), v1 = (j1 <= sw - 1);
    int C0 = v0 ? j0 : 0, C1 = v1 ? j1 : sw - 1;
    float n0, n1;
    if (v0 && v1) {
        float tot = __fadd_rn(w0, w1);
        n0 = __fdiv_rn(w0, tot); n1 = __fdiv_rn(w1, tot);
    } else if (v0) { n0 = 1.0f; n1 = 0.0f; }
    else           { n0 = 0.0f; n1 = 1.0f; }
    g_rtab[idx] = make_float4(n0, n1, __int_as_float(C0), __int_as_float(C1));
}

// ---------------------------------------------------------------------------
// Table-driven bilinear resize (jax half-pixel semantics baked into tables).
__global__ void __launch_bounds__(256) k_resize2(const float* __restrict__ in, int sIn,
                         float* __restrict__ dst, int sOut, int dw, int tab)
{
    int dy  = blockIdx.y;
    int dx0 = (blockIdx.x * 256 + threadIdx.x) * 4;
    if (dx0 >= dw) return;

    float4 ye = g_rtab[tab + dy];
    float n0y = ye.x, n1y = ye.y;
    const float* r0 = in + (size_t)__float_as_int(ye.z) * sIn;
    const float* r1 = in + (size_t)__float_as_int(ye.w) * sIn;

    float res[4];
    int nn = dw - dx0; if (nn > 4) nn = 4;
    #pragma unroll
    for (int c = 0; c < 4; ++c) {
        if (c >= nn) break;
        float4 xe = g_rtab[tab + dx0 + c];
        float n0x = xe.x, n1x = xe.y;
        int cx0 = __float_as_int(xe.z), cx1 = __float_as_int(xe.w);
        float p00 = __ldg(r0 + cx0), p01 = __ldg(r0 + cx1);
        float p10 = __ldg(r1 + cx0), p11 = __ldg(r1 + cx1);
        float c0 = __fadd_rn(__fmul_rn(n0y, p00), __fmul_rn(n1y, p10));
        float c1 = __fadd_rn(__fmul_rn(n0y, p01), __fmul_rn(n1y, p11));
        res[c] = __fadd_rn(__fmul_rn(n0x, c0), __fmul_rn(n1x, c1));
    }
    float* orow = dst + (size_t)dy * sOut;
    if (nn == 4) *(float4*)(orow + dx0) = make_float4(res[0], res[1], res[2], res[3]);
    else for (int c = 0; c < nn; ++c) orow[dx0 + c] = res[c];
}

// ---------------------------------------------------------------------------
__device__ __forceinline__ int reflect_i(int i, int n)
{
    if (i < 0) return -i;
    if (i >= n) return 2 * n - 2 - i;
    return i;
}

// Fused separable 5-tap gaussian blur (reflect): V in registers, H via smem.
__global__ void __launch_bounds__(128) k_blurVH(const float* __restrict__ in,
        float* __restrict__ out, int S, int W, int H,
        float g0, float g1, float g2)
{
    __shared__ __align__(16) float sv[8][512];
    int t  = threadIdx.x;
    int xb = blockIdx.x * 504;
    int yb = blockIdx.y * 8;
    int xg = xb - 4 + t * 4;

    float4 raw[12];
    bool fast = (xg >= 0) && (xg + 4 <= W);
    #pragma unroll
    for (int r = 0; r < 12; ++r) {
        const float* rowp = in + (size_t)reflect_i(yb - 2 + r, H) * S;
        if (fast) {
            raw[r] = __ldg((const float4*)(rowp + xg));
        } else {
            float t0 = __ldg(rowp + reflect_i(xg,     W));
            float t1 = __ldg(rowp + reflect_i(xg + 1, W));
            float t2 = __ldg(rowp + reflect_i(xg + 2, W));
            float t3 = __ldg(rowp + reflect_i(xg + 3, W));
            raw[r] = make_float4(t0, t1, t2, t3);
        }
    }
    #pragma unroll
    for (int r = 0; r < 8; ++r) {
        float4 a = raw[r], b = raw[r+1], c = raw[r+2], d = raw[r+3], e = raw[r+4];
        float4 vb;
        vb.x = fmaf(g0, e.x, fmaf(g1, d.x, fmaf(g2, c.x, fmaf(g1, b.x, g0 * a.x))));
        vb.y = fmaf(g0, e.y, fmaf(g1, d.y, fmaf(g2, c.y, fmaf(g1, b.y, g0 * a.y))));
        vb.z = fmaf(g0, e.z, fmaf(g1, d.z, fmaf(g2, c.z, fmaf(g1, b.z, g0 * a.z))));
        vb.w = fmaf(g0, e.w, fmaf(g1, d.w, fmaf(g2, c.w, fmaf(g1, b.w, g0 * a.w))));
        *(float4*)&sv[r][t * 4] = vb;
    }
    __syncthreads();
    if (t >= 126) return;
    int xo = xb + t * 4;
    if (xo >= W) return;
    #pragma unroll
    for (int r = 0; r < 8; ++r) {
        int yo = yb + r;
        if (yo >= H) break;
        float v[12];
        #pragma unroll
        for (int q = 0; q < 3; ++q) {
            float4 a = *(float4*)&sv[r][t * 4 + q * 4];
            v[q*4] = a.x; v[q*4+1] = a.y; v[q*4+2] = a.z; v[q*4+3] = a.w;
        }
        float res[4];
        #pragma unroll
        for (int c = 0; c < 4; ++c) {
            res[c] = fmaf(g0, v[c + 6], fmaf(g1, v[c + 5],
                     fmaf(g2, v[c + 4], fmaf(g1, v[c + 3], g0 * v[c + 2]))));
        }
        float* orow = out + (size_t)yo * S;
        if (xo + 4 <= W) {
            *(float4*)(orow + xo) = make_float4(res[0], res[1], res[2], res[3]);
        } else {
            for (int c = 0; c < 4; ++c) if (xo + c < W) orow[xo + c] = res[c];
        }
    }
}

// ---------------------------------------------------------------------------
// Merged (all levels) 8-row-tile fused conv + border-mask + row-max + semi-mask.
// Tile: 512 out px x 8 rows. Conv computed for 528 cols (±8 halo), taps from a
// 536-wide x 12-row raw smem tile. Conv tap order identical to prior kernels.
__global__ void __launch_bounds__(128) k_convnms(const float* __restrict__ imgOrig,
        const float* __restrict__ wp, const float* __restrict__ bp)
{
    __shared__ float swt[25];
    __shared__ float sbv;
    __shared__ __align__(16) float raw[12][536];
    __shared__ __align__(16) float sc[8][528];
    __shared__ unsigned char nib[8][128];
    int t = threadIdx.x;
    if (t < 25) swt[t] = __ldg(wp + t);
    if (t == 31) sbv = __ldg(bp);

    int bid = blockIdx.x;
    int l = 5;
    while (bid < c_cumNC[l]) --l;
    int rem  = bid - c_cumNC[l];
    int bx   = c_bx[l];
    int yblk = rem / bx;
    int xblk = rem - yblk * bx;
    int W = c_W[l], H = W, S = c_S[l];
    const float* img;
    switch (l) {
        case 0: img = g_imgup; break;
        case 1: img = imgOrig; break;
        case 2: img = g_img2;  break;
        case 3: img = g_img3;  break;
        case 4: img = g_img4;  break;
        default: img = g_img5; break;
    }
    int y0 = yblk * 8, xb = xblk * 512;

    // load raw tile: rows y0-2..y0+9 (clamped), cols xb-12..xb+523
    bool xfast = (xb >= 12) && (xb + 524 <= W);
    #pragma unroll
    for (int r = 0; r < 12; ++r) {
        int yy = y0 - 2 + r;
        yy = yy < 0 ? 0 : (yy > H - 1 ? H - 1 : yy);
        const float* rp = img + (size_t)yy * S;
        if (xfast) {
            *(float4*)&raw[r][t * 4] = __ldg((const float4*)(rp + xb - 12 + t * 4));
            if (t < 6)
                *(float4*)&raw[r][512 + t * 4] = __ldg((const float4*)(rp + xb + 500 + t * 4));
        } else {
            for (int i = t; i < 536; i += 128) {
                int x = xb - 12 + i;
                x = x < 0 ? 0 : (x > W - 1 ? W - 1 : x);
                raw[r][i] = __ldg(rp + x);
            }
        }
    }
    __syncthreads();

    // conv for 8 rows x 528 cols (col j -> x = xb-8+j)
    for (int r = 0; r < 8; ++r) {
        int yv = y0 + r;
        bool rowok = (yv >= 15 && yv < H - 15);
        #pragma unroll
        for (int seg = 0; seg < 2; ++seg) {
            if (seg == 1 && t >= 4) break;
            int j0 = (seg == 0) ? t * 4 : 512 + t * 4;
            float a0 = sbv, a1 = sbv, a2 = sbv, a3 = sbv;
            #pragma unroll
            for (int ky = 0; ky < 5; ++ky) {
                const float* rr = &raw[r + ky][j0 + 2];
                float v0 = rr[0], v1 = rr[1], v2 = rr[2], v3 = rr[3];
                float v4 = rr[4], v5 = rr[5], v6 = rr[6], v7 = rr[7];
                const float* wr = &swt[ky * 5];
                a0 = fmaf(wr[0], v0, a0); a0 = fmaf(wr[1], v1, a0);
                a0 = fmaf(wr[2], v2, a0); a0 = fmaf(wr[3], v3, a0);
                a0 = fmaf(wr[4], v4, a0);
                a1 = fmaf(wr[0], v1, a1); a1 = fmaf(wr[1], v2, a1);
                a1 = fmaf(wr[2], v3, a1); a1 = fmaf(wr[3], v4, a1);
                a1 = fmaf(wr[4], v5, a1);
                a2 = fmaf(wr[0], v2, a2); a2 = fmaf(wr[1], v3, a2);
                a2 = fmaf(wr[2], v4, a2); a2 = fmaf(wr[3], v5, a2);
                a2 = fmaf(wr[4], v6, a2);
                a3 = fmaf(wr[0], v3, a3); a3 = fmaf(wr[1], v4, a3);
                a3 = fmaf(wr[2], v5, a3); a3 = fmaf(wr[3], v6, a3);
                a3 = fmaf(wr[4], v7, a3);
            }
            int xg = xb - 8 + j0;
            sc[r][j0 + 0] = (rowok && xg + 0 >= 15 && xg + 0 < W - 15) ? a0 : 0.f;
            sc[r][j0 + 1] = (rowok && xg + 1 >= 15 && xg + 1 < W - 15) ? a1 : 0.f;
            sc[r][j0 + 2] = (rowok && xg + 2 >= 15 && xg + 2 < W - 15) ? a2 : 0.f;
            sc[r][j0 + 3] = (rowok && xg + 3 >= 15 && xg + 3 < W - 15) ? a3 : 0.f;
        }
    }
    __syncthreads();

    // row-max + semi-candidate nibbles + rmax store
    float* rbase = g_rmax + c_off[l];
    for (int r = 0; r < 8; ++r) {
        float v[19];
        #pragma unroll
        for (int i = 1; i <= 18; ++i) v[i] = sc[r][t * 4 + i];
        float run = v[15];
        #pragma unroll
        for (int i = 14; i >= 5; --i) run = fmaxf(run, v[i]);
        float suf4 = fmaxf(run, v[4]);
        float suf3 = fmaxf(suf4, v[3]);
        float suf2 = fmaxf(suf3, v[2]);
        float suf1 = fmaxf(suf2, v[1]);
        float r0 = suf1;
        float run2 = v[16];
        float r1 = fmaxf(suf2, run2);
        run2 = fmaxf(run2, v[17]);
        float r2 = fmaxf(suf3, run2);
        run2 = fmaxf(run2, v[18]);
        float r3 = fmaxf(suf4, run2);
        float s0 = v[8], s1 = v[9], s2 = v[10], s3 = v[11];
        unsigned nb = 0;
        if (s0 > 0.f && s0 == r0) nb |= 1u;
        if (s1 > 0.f && s1 == r1) nb |= 2u;
        if (s2 > 0.f && s2 == r2) nb |= 4u;
        if (s3 > 0.f && s3 == r3) nb |= 8u;
        nib[r][t] = (unsigned char)nb;
        int yv = y0 + r;
        int x0 = xb + t * 4;
        if (yv < H && x0 < S)
            *(float4*)(rbase + (size_t)yv * S + x0) = make_float4(r0, r1, r2, r3);
    }
    __syncthreads();

    // assemble & store mask words (one per thread: 8 rows x 16 words)
    {
        int r = t >> 4, w = t & 15;
        unsigned word = 0;
        #pragma unroll
        for (int q = 0; q < 8; ++q)
            word |= ((unsigned)nib[r][w * 8 + q]) << (q * 4);
        int yv = y0 + r;
        int wi = xblk * 16 + w;
        if (yv < H && wi < c_mS[l])
            g_mask[c_moff[l] + yv * c_mS[l] + wi] = word;
    }
}

// ---------------------------------------------------------------------------
// Column-max check over rmax + emission. s recovered from rmax center row.
__global__ void __launch_bounds__(128) k_colcheck()
{
    int bid = blockIdx.x;
    int l = 5;
    while (bid < c_cumNC[l]) --l;
    int rem  = bid - c_cumNC[l];
    int bx   = c_bx[l];
    int yblk = rem / bx;
    int xblk = rem - yblk * bx;
    int W = c_W[l], H = W, S = c_S[l];
    const float* rmax = g_rmax + c_off[l];
    const unsigned* mrow = g_mask + c_moff[l];
    int mS = c_mS[l];

    int x4 = xblk * 512 + threadIdx.x * 4;
    if (x4 >= W) return;
    int y0 = yblk * 8;

    unsigned nb[8]; unsigned any = 0;
    #pragma unroll
    for (int o = 0; o < 8; ++o) {
        int y = y0 + o;
        unsigned m = (y < H) ? __ldg(mrow + y * mS + (x4 >> 5)) : 0u;
        nb[o] = (m >> (x4 & 31)) & 15u;
        any |= nb[o];
    }
    if (!any) return;

    float4 v[22];
    #pragma unroll
    for (int j = 0; j < 22; ++j) {
        int yy = y0 - 7 + j;
        yy = yy < 0 ? 0 : (yy > H - 1 ? H - 1 : yy);
        v[j] = __ldg((const float4*)(rmax + (size_t)yy * S + x4));
    }
    float4 pre[8];
    float4 run = v[14];
    #pragma unroll
    for (int j = 13; j >= 0; --j) {
        run = f4max(run, v[j]);
        if (j <= 7) pre[j] = run;
    }
    float4 run2 = v[15];
    #pragma unroll
    for (int o = 0; o < 8; ++o) {
        int y = y0 + o;
        if (y >= H) break;
        float4 m;
        if (o == 0) m = pre[0];
        else {
            if (o >= 2) run2 = f4max(run2, v[o + 14]);
            m = f4max(pre[o], run2);
        }
        if (!nb[o]) continue;
        float4 ctr = v[o + 7];
        const float* sp = (const float*)&ctr;
        const float* mp = (const float*)&m;
        #pragma unroll
        for (int cc = 0; cc < 4; ++cc) {
            if (!((nb[o] >> cc) & 1u)) continue;
            int x = x4 + cc;
            float s = sp[cc];
            if (s == mp[cc]) {
                unsigned sbits = __float_as_uint(s) | 0x80000000u;
                int pix = y * W + x;
                u64 key = ((u64)sbits << 26) | ((u64)(5 - l) << 23)
                        | (u64)(0x7FFFFF - pix);
                int pos = atomicAdd(&g_cnt[l], 1);
                if (pos < CAP) g_cand[(size_t)l * CAP + pos] = key;
            }
        }
    }
}

// ---------------------------------------------------------------------------
// All 6 per-level radix selects concurrently (block l -> level l).
__global__ void __launch_bounds__(1024) k_select6()
{
    __shared__ int hist[256];
    __shared__ u64 s_pref;
    __shared__ int s_k;
    int l   = blockIdx.x;
    int tid = threadIdx.x;
    const u64* src = g_cand + (size_t)l * CAP;
    int k   = c_k[l];
    int cnt = g_cnt[l];
    if (cnt > CAP) cnt = CAP;
    u64 thr = 0;
    if (cnt > k) {
        if (tid == 0) { s_pref = 0ull; s_k = k; }
        __syncthreads();
        for (int b = 7; b >= 0; --b) {
            if (tid < 256) hist[tid] = 0;
            __syncthreads();
            u64 pref = s_pref;
            u64 maskHi = (b == 7) ? 0ull : (~0ull << (8 * (b + 1)));
            for (int i = tid; i < cnt; i += 1024) {
                u64 key = src[i];
                if ((key & maskHi) == pref)
                    atomicAdd(&hist[(int)((key >> (8 * b)) & 255)], 1);
            }
            __syncthreads();
            if (tid == 0) {
                int kk = s_k, cum = 0, d = 255;
                for (; d >= 0; --d) { cum += hist[d]; if (cum >= kk) break; }
                s_k = kk - (cum - hist[d]);
                s_pref = s_pref | ((u64)d << (8 * b));
            }
            __syncthreads();
        }
        thr = s_pref;
    }
    __syncthreads();
    for (int i = tid; i < cnt; i += 1024) {
        u64 key = src[i];
        if (key >= thr) {
            int p = atomicAdd(&g_cnt[6], 1);
            g_pool[p] = key;
        }
    }
}

// ---------------------------------------------------------------------------
// Final: radix-select top 2048 -> smem, bitonic sort, decode, emit.
__global__ void __launch_bounds__(1024) k_final(float* __restrict__ out, int out_size)
{
    __shared__ int hist[256];
    __shared__ u64 s_pref;
    __shared__ int s_k, s_cnt;
    __shared__ u64 s[2048];
    int tid = threadIdx.x;
    int cnt = g_cnt[6];
    if (cnt > 12288) cnt = 12288;

    u64 thr = 0;
    if (cnt > 2048) {
        if (tid == 0) { s_pref = 0ull; s_k = 2048; }
        __syncthreads();
        for (int b = 7; b >= 0; --b) {
            if (tid < 256) hist[tid] = 0;
            __syncthreads();
            u64 pref = s_pref;
            u64 maskHi = (b == 7) ? 0ull : (~0ull << (8 * (b + 1)));
            for (int i = tid; i < cnt; i += 1024) {
                u64 key = g_pool[i];
                if ((key & maskHi) == pref)
                    atomicAdd(&hist[(int)((key >> (8 * b)) & 255)], 1);
            }
            __syncthreads();
            if (tid == 0) {
                int kk = s_k, cum = 0, d = 255;
                for (; d >= 0; --d) { cum += hist[d]; if (cum >= kk) break; }
                s_k = kk - (cum - hist[d]);
                s_pref = s_pref | ((u64)d << (8 * b));
            }
            __syncthreads();
        }
        thr = s_pref;
    }
    s[tid] = 0ull; s[tid + 1024] = 0ull;
    if (tid == 0) s_cnt = 0;
    __syncthreads();
    for (int i = tid; i < cnt; i += 1024) {
        u64 key = g_pool[i];
        if (key >= thr) {
            int p = atomicAdd(&s_cnt, 1);
            if (p < 2048) s[p] = key;
        }
    }
    __syncthreads();

    for (int ksz = 2; ksz <= 2048; ksz <<= 1) {
        for (int j = ksz >> 1; j > 0; j >>= 1) {
            #pragma unroll
            for (int half = 0; half < 2; ++half) {
                int i = tid + half * 1024;
                int ixj = i ^ j;
                if (ixj > i) {
                    u64 a = s[i], b = s[ixj];
                    bool asc = ((i & ksz) == 0);
                    if (asc ? (a > b) : (a < b)) { s[i] = b; s[ixj] = a; }
                }
            }
            __syncthreads();
        }
    }

    bool haveL = (out_size >= 12288);
    bool haveR = (out_size >= 14336) || (out_size < 12288);
    int rbase  = (out_size >= 14336) ? 12288 : 0;
    for (int r = tid; r < 2048; r += 1024) {
        u64 key = s[2047 - r];
        int pix = 0x7FFFFF - (int)(key & 0x7FFFFF);
        int lvl = 5 - (int)((key >> 23) & 7);
        float scv = __uint_as_float((unsigned)(key >> 26) & 0x7FFFFFFFu);
        int Wl = c_W[lvl];
        int py = pix / Wl, px = pix - py * Wl;
        float f  = c_fact[lvl], sg = c_scal[lvl];
        float fx = __fmul_rn((float)px, f);
        float fy = __fmul_rn((float)py, f);
        if (haveL) {
            float* L = out + (size_t)r * 6;
            L[0] = sg; L[1] = 0.f; L[2] = fx;
            L[3] = 0.f; L[4] = sg; L[5] = fy;
        }
        if (haveR) out[rbase + r] = scv;
    }
}

// ---------------------------------------------------------------------------
extern "C" void kernel_launch(void* const* d_in, const int* in_sizes, int n_in,
                              void* d_out, int out_size)
{
    const float* img = (const float*)d_in[0];
    const float* cw  = (const float*)d_in[1];
    const float* cb  = (const float*)d_in[2];
    float* out = (float*)d_out;

    void *p_up, *p_i2, *p_i3, *p_i4, *p_i5, *p_bB;
    cudaGetSymbolAddress(&p_up, g_imgup);
    cudaGetSymbolAddress(&p_i2, g_img2);
    cudaGetSymbolAddress(&p_i3, g_img3);
    cudaGetSymbolAddress(&p_i4, g_img4);
    cudaGetSymbolAddress(&p_i5, g_img5);
    cudaGetSymbolAddress(&p_bB, g_blurB);
    float *imgup=(float*)p_up, *img2=(float*)p_i2, *img3=(float*)p_i3,
          *img4=(float*)p_i4, *img5=(float*)p_i5, *bB=(float*)p_bB;

    // gaussian 5-tap, sigma=1 (identical host math to passing kernels)
    float gx[5] = {4.f, 1.f, 0.f, 1.f, 4.f};
    float g[5], gs = 0.f;
    for (int i = 0; i < 5; ++i) { g[i] = expf(-gx[i] * 0.5f); gs += g[i]; }
    for (int i = 0; i < 5; ++i) g[i] /= gs;

    k_init<<<26, 256>>>();

    // level 0: upscale 2048 -> 2896 (table at offset 0)
    k_resize2<<<dim3(3, 2896), 256>>>(img, 2048, imgup, 2896, 2896, 0);

    // pyrdown chain: blur (fused V+H) then table-driven resize
    k_blurVH<<<dim3(5, 256), 128>>>(img, bB, 2048, 2048, 2048, g[0], g[1], g[2]);
    k_resize2<<<dim3(2, 1448), 256>>>(bB, 2048, img2, 1448, 1448, 2896);

    k_blurVH<<<dim3(3, 181), 128>>>(img2, bB, 1448, 1448, 1448, g[0], g[1], g[2]);
    k_resize2<<<dim3(1, 1023), 256>>>(bB, 1448, img3, 1024, 1023, 4344);

    k_blurVH<<<dim3(3, 128), 128>>>(img3, bB, 1024, 1023, 1023, g[0], g[1], g[2]);
    k_resize2<<<dim3(1, 723), 256>>>(bB, 1024, img4, 724, 723, 5367);

    k_blurVH<<<dim3(2, 91), 128>>>(img4, bB, 724, 723, 723, g[0], g[1], g[2]);
    k_resize2<<<dim3(1, 511), 256>>>(bB, 724, img5, 512, 511, 6090);

    // merged detection across all 6 levels
    k_convnms <<<4241, 128>>>(img, cw, cb);
    k_colcheck<<<4241, 128>>>();

    // selection
    k_select6<<<6, 1024>>>();
    k_final<<<1, 1024>>>(out, out_size);
}